// round 13
// baseline (speedup 1.0000x reference)
#include <cuda_runtime.h>
#include <cuda_fp16.h>
#include <math.h>
#include <stdint.h>

#define NTOK 8192
#define DIM  1024
#define NEXP 32
#define HID  128
#define TK   4
#define SHID 512
#define NROWS (NTOK*TK)
#define CAP  32768

// ---------------- scratch (device globals; no allocations) ----------------
__device__ __align__(16) int   g_cursor[NEXP];
__device__ __align__(16) int   g_bucket_src[(size_t)NEXP * CAP];
__device__ __align__(16) float g_bucket_sc [(size_t)NEXP * CAP];
__device__ __align__(16) __half g_xh[(size_t)NTOK * DIM];
__device__ __align__(16) __half g_gwh[(size_t)NEXP * HID * DIM];
__device__ __align__(16) __half g_uwh[(size_t)NEXP * HID * DIM];
__device__ __align__(16) __half g_dwh[(size_t)NEXP * DIM * HID];
__device__ __align__(16) __half g_sgwh[(size_t)SHID * DIM];
__device__ __align__(16) __half g_suwh[(size_t)SHID * DIM];
__device__ __align__(16) __half g_sdwh[(size_t)DIM * SHID];
__device__ __align__(16) __half g_Hh[(size_t)NROWS * HID];
__device__ __align__(16) __half g_sHh[(size_t)NTOK * SHID];
__device__ __align__(16) __half g_Y[(size_t)NROWS * DIM];

// ---------------- helpers ---------------------------------------------------
__device__ __forceinline__ uint32_t s2u(const void* p) {
    uint32_t r;
    asm("{.reg .u64 t; cvta.to.shared.u64 t, %1; cvt.u32.u64 %0, t;}" : "=r"(r) : "l"(p));
    return r;
}
__device__ __forceinline__ uint32_t swz(uint32_t b) { return b ^ ((b >> 3) & 0x70); }

__device__ __forceinline__ void cpa16h(uint32_t daddr, const __half* src, bool pred) {
    int sz = pred ? 16 : 0;
    asm volatile("cp.async.cg.shared.global [%0], [%1], 16, %2;\n"
                 :: "r"(daddr), "l"(src), "r"(sz));
}
__device__ __forceinline__ void cp_commit() {
    asm volatile("cp.async.commit_group;\n" ::);
}
template<int N> __device__ __forceinline__ void cp_wait() {
    asm volatile("cp.async.wait_group %0;\n" :: "n"(N));
}
__device__ __forceinline__ void mma16(float* c, const uint32_t* a, const uint32_t* b) {
    asm volatile(
        "mma.sync.aligned.m16n8k16.row.col.f32.f16.f16.f32 "
        "{%0,%1,%2,%3}, {%4,%5,%6,%7}, {%8,%9}, {%0,%1,%2,%3};"
        : "+f"(c[0]), "+f"(c[1]), "+f"(c[2]), "+f"(c[3])
        : "r"(a[0]), "r"(a[1]), "r"(a[2]), "r"(a[3]), "r"(b[0]), "r"(b[1]));
}
__device__ __forceinline__ float silu_mul(float g, float u) {
    return g / (1.f + __expf(-g)) * u;
}
__device__ __forceinline__ void ldsm4(uint32_t* r, uint32_t addr) {
    asm volatile("ldmatrix.sync.aligned.m8n8.x4.shared.b16 {%0,%1,%2,%3}, [%4];"
        : "=r"(r[0]), "=r"(r[1]), "=r"(r[2]), "=r"(r[3]) : "r"(addr));
}

#define TILE_BYTES 16384u
#define SMEM_GU4   (4 * 3 * TILE_BYTES)      // 192 KB (gu, 4-stage)
#define SMEM_DOWN  ((2 + 3) * TILE_BYTES)    // 80 KB
#define SMEM_FIN   (3 * 3 * TILE_BYTES)      // 144 KB (final 128x256, 3-stage)

// single-B k64 compute (256 threads, warp tile 32x64)
__device__ __forceinline__ void compute_k64h(
    uint32_t sAt, uint32_t sBt, int wm, int wn, int lane, float acc[2][8][4]) {
    int ar = lane & 15, ac = lane >> 4;
    int br = (lane & 7) + ((lane >> 4) & 1) * 8;
    int bc = (lane >> 3) & 1;
#pragma unroll
    for (int ks = 0; ks < 4; ks++) {
        uint32_t af[2][4];
#pragma unroll
        for (int mt = 0; mt < 2; mt++)
            ldsm4(af[mt], sAt + swz((uint32_t)((wm + mt * 16 + ar) * 128 + (ks * 2 + ac) * 16)));
        uint32_t bf[8][2];
#pragma unroll
        for (int j = 0; j < 4; j++) {
            uint32_t r[4];
            ldsm4(r, sBt + swz((uint32_t)((wn + 16 * j + br) * 128 + (ks * 2 + bc) * 16)));
            bf[2*j][0] = r[0]; bf[2*j][1] = r[1]; bf[2*j+1][0] = r[2]; bf[2*j+1][1] = r[3];
        }
#pragma unroll
        for (int mt = 0; mt < 2; mt++)
#pragma unroll
            for (int nt = 0; nt < 8; nt++) mma16(acc[mt][nt], af[mt], bf[nt]);
    }
}

// fused gate+up compute, 512 threads: warp tile 32x32 per output matrix
__device__ __forceinline__ void compute_k64h_gu512(
    uint32_t sAt, uint32_t sBg, uint32_t sBu, int wm, int wn, int lane,
    float accg[2][4][4], float accu[2][4][4]) {
    int ar = lane & 15, ac = lane >> 4;
    int br = (lane & 7) + ((lane >> 4) & 1) * 8;
    int bc = (lane >> 3) & 1;
#pragma unroll
    for (int ks = 0; ks < 4; ks++) {
        uint32_t af[2][4];
#pragma unroll
        for (int mt = 0; mt < 2; mt++)
            ldsm4(af[mt], sAt + swz((uint32_t)((wm + mt * 16 + ar) * 128 + (ks * 2 + ac) * 16)));
        uint32_t bf[4][2];
#pragma unroll
        for (int j = 0; j < 2; j++) {
            uint32_t r[4];
            ldsm4(r, sBg + swz((uint32_t)((wn + 16 * j + br) * 128 + (ks * 2 + bc) * 16)));
            bf[2*j][0] = r[0]; bf[2*j][1] = r[1]; bf[2*j+1][0] = r[2]; bf[2*j+1][1] = r[3];
        }
#pragma unroll
        for (int mt = 0; mt < 2; mt++)
#pragma unroll
            for (int nt = 0; nt < 4; nt++) mma16(accg[mt][nt], af[mt], bf[nt]);
#pragma unroll
        for (int j = 0; j < 2; j++) {
            uint32_t r[4];
            ldsm4(r, sBu + swz((uint32_t)((wn + 16 * j + br) * 128 + (ks * 2 + bc) * 16)));
            bf[2*j][0] = r[0]; bf[2*j][1] = r[1]; bf[2*j+1][0] = r[2]; bf[2*j+1][1] = r[3];
        }
#pragma unroll
        for (int mt = 0; mt < 2; mt++)
#pragma unroll
            for (int nt = 0; nt < 4; nt++) mma16(accu[mt][nt], af[mt], bf[nt]);
    }
}

// ---------------- K0: convW (6 weight arrays, 32 floats/thread) + init --------
#define NG8  ((unsigned)(NEXP * HID * DIM / 8))     // 524288
#define NS8  ((unsigned)(SHID * DIM / 8))           // 65536
#define W1 (NG8)
#define W2 (2u * NG8)
#define W3 (3u * NG8)
#define W4 (W3 + NS8)
#define W5 (W4 + NS8)
#define W6 (W5 + NS8)

__global__ __launch_bounds__(256) void convw_kernel(
    const float* __restrict__ gw, const float* __restrict__ uw,
    const float* __restrict__ dw, const float* __restrict__ sgw,
    const float* __restrict__ suw, const float* __restrict__ sdw) {
    if (blockIdx.x == 0 && threadIdx.x < NEXP) g_cursor[threadIdx.x] = 0;
    unsigned q = (blockIdx.x * 256 + threadIdx.x) * 4;   // 4 chunks of 8 = 32 floats
    if (q >= W6) return;
    const float* src; __half* dst; unsigned base;
    if      (q < W1) { src = gw;  dst = g_gwh;  base = 0; }
    else if (q < W2) { src = uw;  dst = g_uwh;  base = W1; }
    else if (q < W3) { src = dw;  dst = g_dwh;  base = W2; }
    else if (q < W4) { src = sgw; dst = g_sgwh; base = W3; }
    else if (q < W5) { src = suw; dst = g_suwh; base = W4; }
    else             { src = sdw; dst = g_sdwh; base = W5; }
    size_t e = (size_t)(q - base) * 8;
    const float4* s = (const float4*)(src + e);
    float4 v[8];
#pragma unroll
    for (int i = 0; i < 8; i++) v[i] = s[i];
#pragma unroll
    for (int i = 0; i < 4; i++) {
        __half2 h[4];
        h[0] = __floats2half2_rn(v[2*i].x, v[2*i].y);
        h[1] = __floats2half2_rn(v[2*i].z, v[2*i].w);
        h[2] = __floats2half2_rn(v[2*i+1].x, v[2*i+1].y);
        h[3] = __floats2half2_rn(v[2*i+1].z, v[2*i+1].w);
        *(uint4*)(dst + e + i * 8) = *(uint4*)h;
    }
}

// ---------------- K1: router + softmax + top4 + scatter + x->fp16 -------------
__global__ __launch_bounds__(256) void router_scatter_kernel(
    const float* __restrict__ x, const float* __restrict__ rw,
    const float* __restrict__ rb) {
    __shared__ float xs[8 * DIM];
    int tok0 = blockIdx.x * 8;
    int t = threadIdx.x;
#pragma unroll
    for (int i = 0; i < 8; i++) {
        int s = t + i * 256;
        int r = s >> 8; int q = s & 255;
        *(float4*)(xs + r * DIM + q * 4) =
            *(const float4*)(x + (size_t)(tok0 + r) * DIM + q * 4);
    }
    __syncthreads();
    // emit fp16 x (8 tokens x 1024) — 32 floats per thread
#pragma unroll
    for (int i = 0; i < 4; i++) {
        int c = (t + i * 256) * 8;          // element offset within 8192
        const float4* sv = (const float4*)(xs + c);
        float4 a = sv[0], b = sv[1];
        __half2 h[4];
        h[0] = __floats2half2_rn(a.x, a.y); h[1] = __floats2half2_rn(a.z, a.w);
        h[2] = __floats2half2_rn(b.x, b.y); h[3] = __floats2half2_rn(b.z, b.w);
        *(uint4*)(g_xh + (size_t)tok0 * DIM + c) = *(uint4*)h;
    }
    int tl = t >> 5, lane = t & 31;
    int tok = tok0 + tl;
    float acc = rb[lane];
    const float4* xv = (const float4*)(xs + tl * DIM);
    const float4* wv = (const float4*)(rw + (size_t)lane * DIM);
#pragma unroll 4
    for (int q = 0; q < DIM / 4; q++) {
        float4 a = xv[q], b = wv[q];
        acc = fmaf(a.x, b.x, acc); acc = fmaf(a.y, b.y, acc);
        acc = fmaf(a.z, b.z, acc); acc = fmaf(a.w, b.w, acc);
    }
    float m = acc;
#pragma unroll
    for (int o = 16; o; o >>= 1) m = fmaxf(m, __shfl_xor_sync(~0u, m, o));
    float p = __expf(acc - m);
    float s = p;
#pragma unroll
    for (int o = 16; o; o >>= 1) s += __shfl_xor_sync(~0u, s, o);
    float sc = p / s;
    float cs[TK]; int ci[TK];
    float cur = sc;
#pragma unroll
    for (int k = 0; k < TK; k++) {
        float v = cur; int vi = lane;
#pragma unroll
        for (int o = 16; o; o >>= 1) {
            float ov = __shfl_xor_sync(~0u, v, o);
            int   oi = __shfl_xor_sync(~0u, vi, o);
            if (ov > v || (ov == v && oi < vi)) { v = ov; vi = oi; }
        }
        cs[k] = v; ci[k] = vi;
        if (lane == vi) cur = -1.f;
    }
    float inv = 1.f / fmaxf(cs[0] + cs[1] + cs[2] + cs[3], 1e-12f);
    if (lane < TK) {
        int e = ci[lane];
        int pos = atomicAdd(&g_cursor[e], 1);
        g_bucket_src[(size_t)e * CAP + pos] = tok * TK + lane;
        g_bucket_sc [(size_t)e * CAP + pos] = cs[lane] * inv;
    }
}

// ---------------- K2: POOLED gate+up (routed + shared), 4-stage ---------------
__global__ __launch_bounds__(512) void gu_all_kernel(
    const __half* __restrict__ gwp, const __half* __restrict__ uwp,
    const __half* __restrict__ sgwp, const __half* __restrict__ suwp) {
    int by = blockIdx.y;
    int tile0 = blockIdx.x * 128;
    int t = threadIdx.x;
    extern __shared__ __half smh[];
    uint32_t sA = s2u(smh), sBg = sA + 4 * TILE_BYTES, sBu = sA + 8 * TILE_BYTES;
    __shared__ int srcs[128];

    int cnt, ostride, shift;
    const __half *Wg, *Wu;
    __half* outp;
    if (by < NEXP) {
        cnt = g_cursor[by];
        if (tile0 >= cnt) return;
        size_t off = (size_t)by * CAP;
        Wg = gwp + (size_t)by * HID * DIM;
        Wu = uwp + (size_t)by * HID * DIM;
        outp = g_Hh; ostride = HID; shift = 2;
        if (t < 128) { int m = tile0 + t; srcs[t] = (m < cnt) ? g_bucket_src[off + m] : -1; }
    } else {
        int nb = (by - NEXP) * 128;
        cnt = NTOK;
        Wg = sgwp + (size_t)nb * DIM;
        Wu = suwp + (size_t)nb * DIM;
        outp = g_sHh + nb; ostride = SHID; shift = 0;
        if (t < 128) srcs[t] = tile0 + t;
    }
    __syncthreads();

    int rw_[2], cw[2]; const __half* aP[2]; const __half* gP[2]; const __half* uP[2]; bool av[2];
#pragma unroll
    for (int i = 0; i < 2; i++) {
        int c = t + i * 512; rw_[i] = c >> 3; cw[i] = c & 7;
        int s0 = srcs[rw_[i]];
        av[i] = s0 >= 0;
        int tok = (av[i] ? s0 : 0) >> shift;
        aP[i] = g_xh + (size_t)tok * DIM + cw[i] * 8;
        gP[i] = Wg + (size_t)rw_[i] * DIM + cw[i] * 8;
        uP[i] = Wu + (size_t)rw_[i] * DIM + cw[i] * 8;
    }
    int lane = t & 31, wid = t >> 5;
    int wm = (wid & 3) * 32, wn = (wid >> 2) * 32, g = lane >> 2, tig = lane & 3;
    float accg[2][4][4] = {}, accu[2][4][4] = {};

#define GU_ISSUE(st, kb)                                                        \
    {                                                                           \
        uint32_t so = (uint32_t)(st) * TILE_BYTES;                              \
        _Pragma("unroll")                                                       \
        for (int i = 0; i < 2; i++) {                                           \
            uint32_t o = swz((uint32_t)(rw_[i] * 128 + cw[i] * 16));            \
            cpa16h(sA + so + o, aP[i] + (kb), av[i]);                           \
            cpa16h(sBg + so + o, gP[i] + (kb), true);                           \
            cpa16h(sBu + so + o, uP[i] + (kb), true);                           \
        }                                                                       \
        cp_commit();                                                            \
    }

    const int NIT = DIM / 64;     // 16
    GU_ISSUE(0, 0) GU_ISSUE(1, 64) GU_ISSUE(2, 128)
    for (int it = 0; it < NIT; it++) {
        if (it + 2 < NIT) cp_wait<2>();
        else if (it + 1 < NIT) cp_wait<1>();
        else cp_wait<0>();
        __syncthreads();
        int st = it & 3;
        compute_k64h_gu512(sA + st * TILE_BYTES, sBg + st * TILE_BYTES,
                           sBu + st * TILE_BYTES, wm, wn, lane, accg, accu);
        int nx = it + 3;
        if (nx < NIT) GU_ISSUE(nx & 3, nx * 64)
    }
#undef GU_ISSUE

#pragma unroll
    for (int mt = 0; mt < 2; mt++) {
        int rL = wm + mt * 16 + g;
        int s0 = srcs[rL], s1 = srcs[rL + 8];
#pragma unroll
        for (int nt = 0; nt < 4; nt++) {
            int col = wn + nt * 8 + 2 * tig;
            if (s0 >= 0) {
                __half2 h = __floats2half2_rn(
                    silu_mul(accg[mt][nt][0], accu[mt][nt][0]),
                    silu_mul(accg[mt][nt][1], accu[mt][nt][1]));
                *(__half2*)(outp + (size_t)s0 * ostride + col) = h;
            }
            if (s1 >= 0) {
                __half2 h = __floats2half2_rn(
                    silu_mul(accg[mt][nt][2], accu[mt][nt][2]),
                    silu_mul(accg[mt][nt][3], accu[mt][nt][3]));
                *(__half2*)(outp + (size_t)s1 * ostride + col) = h;
            }
        }
    }
}

// ---------------- K3: A-resident down GEMM (unchanged) -------------------------
__global__ __launch_bounds__(256, 2) void moe_down_kernel(const __half* __restrict__ dwp) {
    int e = blockIdx.y;
    int cnt = g_cursor[e];
    int tile0 = blockIdx.x * 128;
    if (tile0 >= cnt) return;
    size_t off = (size_t)e * CAP;
    const __half* W = dwp + (size_t)e * DIM * HID;
    extern __shared__ __half smh[];
    uint32_t sA = s2u(smh);
    uint32_t sW = sA + 2 * TILE_BYTES;
    __shared__ float scs[128];
    __shared__ int srcsD[128];
    int t = threadIdx.x;
    if (t < 128) {
        int m = tile0 + t;
        bool v = m < cnt;
        srcsD[t] = v ? g_bucket_src[off + m] : -1;
        scs[t]  = v ? g_bucket_sc[off + m] : 0.f;
    }
    __syncthreads();

    int rw_[4], cw[4]; uint32_t so_[4]; const __half* aP[4]; bool av[4];
#pragma unroll
    for (int i = 0; i < 4; i++) {
        int c = t + i * 256; rw_[i] = c >> 3; cw[i] = c & 7;
        so_[i] = swz((uint32_t)(rw_[i] * 128 + cw[i] * 16));
        int s0 = srcsD[rw_[i]];
        av[i] = s0 >= 0;
        aP[i] = g_Hh + (size_t)(av[i] ? s0 : 0) * HID + cw[i] * 8;
    }

#define W_ISSUE(j)                                                              \
    {                                                                           \
        int nbv = (j) >> 1, kv = (j) & 1;                                       \
        uint32_t slot = ((uint32_t)(j) % 3) * TILE_BYTES;                       \
        _Pragma("unroll")                                                       \
        for (int i = 0; i < 4; i++)                                             \
            cpa16h(sW + slot + so_[i],                                          \
                   W + (size_t)(nbv * 128 + rw_[i]) * HID + kv * 64 + cw[i] * 8, true); \
        cp_commit();                                                            \
    }

#pragma unroll
    for (int i = 0; i < 4; i++) {
        cpa16h(sA + so_[i], aP[i], av[i]);
        cpa16h(sA + TILE_BYTES + so_[i], aP[i] + 64, av[i]);
    }
    {
#pragma unroll
        for (int i = 0; i < 4; i++)
            cpa16h(sW + so_[i], W + (size_t)rw_[i] * HID + cw[i] * 8, true);
        cp_commit();
    }
    W_ISSUE(1)

    int lane = t & 31, wid = t >> 5;
    int wm = (wid & 3) * 32, wn = (wid >> 2) * 64, g = lane >> 2, tig = lane & 3;
    float acc[2][8][4] = {};

    for (int j = 0; j < 16; j++) {
        if (j + 1 < 16) cp_wait<1>(); else cp_wait<0>();
        __syncthreads();
        compute_k64h(sA + (j & 1) * TILE_BYTES, sW + (j % 3) * TILE_BYTES, wm, wn, lane, acc);
        int nx = j + 2;
        if (nx < 16) W_ISSUE(nx)
        if (j & 1) {
            int nb = j >> 1;
#pragma unroll
            for (int mt = 0; mt < 2; mt++) {
                int rL = wm + mt * 16 + g;
                int s0 = srcsD[rL], s1 = srcsD[rL + 8];
#pragma unroll
                for (int nt = 0; nt < 8; nt++) {
                    int col = nb * 128 + wn + nt * 8 + 2 * tig;
                    if (s0 >= 0) {
                        float s = scs[rL];
                        *(__half2*)(g_Y + (size_t)s0 * DIM + col) =
                            __floats2half2_rn(acc[mt][nt][0] * s, acc[mt][nt][1] * s);
                    }
                    if (s1 >= 0) {
                        float s = scs[rL + 8];
                        *(__half2*)(g_Y + (size_t)s1 * DIM + col) =
                            __floats2half2_rn(acc[mt][nt][2] * s, acc[mt][nt][3] * s);
                    }
                }
            }
#pragma unroll
            for (int mt = 0; mt < 2; mt++)
#pragma unroll
                for (int nt = 0; nt < 8; nt++)
#pragma unroll
                    for (int v = 0; v < 4; v++) acc[mt][nt][v] = 0.f;
        }
    }
#undef W_ISSUE
}

// ---------------- K4: final GEMM 128x256 (512 thr) + Y gather -> out -----------
// grid (64, 4). 16 warps: 4m x 4n, warp tile 32x64. B tile 256x64.
__global__ __launch_bounds__(512) void final_kernel(
    const __half* __restrict__ sdwp, float* __restrict__ out) {
    int tile0 = blockIdx.x * 128;
    int nb = blockIdx.y * 256;
    extern __shared__ __half smh[];
    uint32_t sA = s2u(smh);                         // 3 x 16 KB
    uint32_t sB = sA + 3 * TILE_BYTES;              // 3 x 32 KB
    int t = threadIdx.x;

    // A: 2 chunks/thread (1024 chunks), B: 4 chunks/thread (2048 chunks)
    int arw[2], acw[2]; const __half* aP[2];
#pragma unroll
    for (int i = 0; i < 2; i++) {
        int c = t + i * 512; arw[i] = c >> 3; acw[i] = c & 7;
        aP[i] = g_sHh + (size_t)(tile0 + arw[i]) * SHID + acw[i] * 8;
    }
    int brw[4], bcw[4]; const __half* bP[4];
#pragma unroll
    for (int i = 0; i < 4; i++) {
        int c = t + i * 512; brw[i] = c >> 3; bcw[i] = c & 7;
        bP[i] = sdwp + (size_t)(nb + brw[i]) * SHID + bcw[i] * 8;
    }
    int lane = t & 31, wid = t >> 5;
    int wm = (wid & 3) * 32, wn = (wid >> 2) * 64, g = lane >> 2, tig = lane & 3;
    float acc[2][8][4] = {};

#define FIN_ISSUE(st, kb)                                                       \
    {                                                                           \
        uint32_t soA = (uint32_t)(st) * TILE_BYTES;                             \
        uint32_t soB = (uint32_t)(st) * 2 * TILE_BYTES;                         \
        _Pragma("unroll")                                                       \
        for (int i = 0; i < 2; i++)                                             \
            cpa16h(sA + soA + swz((uint32_t)(arw[i] * 128 + acw[i] * 16)),      \
                   aP[i] + (kb), true);                                         \
        _Pragma("unroll")                                                       \
        for (int i = 0; i < 4; i++)                                             \
            cpa16h(sB + soB + swz((uint32_t)(brw[i] * 128 + bcw[i] * 16)),      \
                   bP[i] + (kb), true);                                         \
        cp_commit();                                                            \
    }

    {
        const int NIT = SHID / 64;   // 8
        FIN_ISSUE(0, 0) FIN_ISSUE(1, 64)
        for (int it = 0; it < NIT; it++) {
            if (it + 1 < NIT) cp_wait<1>(); else cp_wait<0>();
            __syncthreads();
            int st = it % 3;
            compute_k64h(sA + st * TILE_BYTES, sB + st * 2 * TILE_BYTES, wm, wn, lane, acc);
            int nx = it + 2;
            if (nx < NIT) FIN_ISSUE(nx % 3, nx * 64)
        }
    }
#undef FIN_ISSUE

#pragma unroll
    for (int mt = 0; mt < 2; mt++) {
        int r0 = tile0 + wm + mt * 16 + g;
        const __half* ya = g_Y + (size_t)r0 * TK * DIM;
#pragma unroll
        for (int nt = 0; nt < 8; nt++) {
            int col = nb + wn + nt * 8 + 2 * tig;
            float2 f0 = __half22float2(*(const __half2*)(ya + col));
            float2 f1 = __half22float2(*(const __half2*)(ya + DIM + col));
            float2 f2 = __half22float2(*(const __half2*)(ya + 2 * DIM + col));
            float2 f3 = __half22float2(*(const __half2*)(ya + 3 * DIM + col));
            float2 ra;
            ra.x = acc[mt][nt][0] + f0.x + f1.x + f2.x + f3.x;
            ra.y = acc[mt][nt][1] + f0.y + f1.y + f2.y + f3.y;
            *(float2*)(out + (size_t)r0 * DIM + col) = ra;
            const __half* yb = ya + 8 * TK * DIM;
            float2 z0 = __half22float2(*(const __half2*)(yb + col));
            float2 z1 = __half22float2(*(const __half2*)(yb + DIM + col));
            float2 z2 = __half22float2(*(const __half2*)(yb + 2 * DIM + col));
            float2 z3 = __half22float2(*(const __half2*)(yb + 3 * DIM + col));
            float2 rb;
            rb.x = acc[mt][nt][2] + z0.x + z1.x + z2.x + z3.x;
            rb.y = acc[mt][nt][3] + z0.y + z1.y + z2.y + z3.y;
            *(float2*)(out + (size_t)(r0 + 8) * DIM + col) = rb;
        }
    }
}

// ---------------- launch ---------------------------------------------------------
extern "C" void kernel_launch(void* const* d_in, const int* in_sizes, int n_in,
                              void* d_out, int out_size) {
    const float* x   = (const float*)d_in[0];
    const float* rw  = (const float*)d_in[1];
    const float* rb  = (const float*)d_in[2];
    const float* gw  = (const float*)d_in[3];
    const float* uw  = (const float*)d_in[4];
    const float* dw  = (const float*)d_in[5];
    const float* sgw = (const float*)d_in[6];
    const float* suw = (const float*)d_in[7];
    const float* sdw = (const float*)d_in[8];
    float* out = (float*)d_out;

    static __half *p_gwh = nullptr, *p_uwh, *p_dwh, *p_sgwh, *p_suwh, *p_sdwh;
    if (!p_gwh) {
        cudaGetSymbolAddress((void**)&p_gwh,  g_gwh);
        cudaGetSymbolAddress((void**)&p_uwh,  g_uwh);
        cudaGetSymbolAddress((void**)&p_dwh,  g_dwh);
        cudaGetSymbolAddress((void**)&p_sgwh, g_sgwh);
        cudaGetSymbolAddress((void**)&p_suwh, g_suwh);
        cudaGetSymbolAddress((void**)&p_sdwh, g_sdwh);
    }

    cudaFuncSetAttribute(gu_all_kernel,   cudaFuncAttributeMaxDynamicSharedMemorySize, SMEM_GU4);
    cudaFuncSetAttribute(moe_down_kernel, cudaFuncAttributeMaxDynamicSharedMemorySize, SMEM_DOWN);
    cudaFuncSetAttribute(final_kernel,    cudaFuncAttributeMaxDynamicSharedMemorySize, SMEM_FIN);

    convw_kernel<<<(W6 / 4 + 255) / 256, 256>>>(gw, uw, dw, sgw, suw, sdw);          // 0
    router_scatter_kernel<<<NTOK / 8, 256>>>(x, rw, rb);                             // 1
    gu_all_kernel<<<dim3(64, NEXP + 4), 512, SMEM_GU4>>>(p_gwh, p_uwh, p_sgwh, p_suwh); // 2
    moe_down_kernel<<<dim3(64, NEXP), 256, SMEM_DOWN>>>(p_dwh);                      // 3 <- profiled
    final_kernel<<<dim3(64, 4), 512, SMEM_FIN>>>(p_sdwh, out);                       // 4
}

// round 14
// speedup vs baseline: 1.0148x; 1.0148x over previous
#include <cuda_runtime.h>
#include <cuda_fp16.h>
#include <math.h>
#include <stdint.h>

#define NTOK 8192
#define DIM  1024
#define NEXP 32
#define HID  128
#define TK   4
#define SHID 512
#define NROWS (NTOK*TK)
#define CAP  32768

// ---------------- scratch (device globals; no allocations) ----------------
__device__ __align__(16) int   g_cursor[NEXP];
__device__ __align__(16) int   g_bucket_src[(size_t)NEXP * CAP];
__device__ __align__(16) float g_bucket_sc [(size_t)NEXP * CAP];
__device__ __align__(16) __half g_xh[(size_t)NTOK * DIM];
__device__ __align__(16) __half g_gwh[(size_t)NEXP * HID * DIM];
__device__ __align__(16) __half g_uwh[(size_t)NEXP * HID * DIM];
__device__ __align__(16) __half g_dwh[(size_t)NEXP * DIM * HID];
__device__ __align__(16) __half g_sgwh[(size_t)SHID * DIM];
__device__ __align__(16) __half g_suwh[(size_t)SHID * DIM];
__device__ __align__(16) __half g_sdwh[(size_t)DIM * SHID];
__device__ __align__(16) __half g_sHh[(size_t)NTOK * SHID];
__device__ __align__(16) __half g_Y[(size_t)NROWS * DIM];

// ---------------- helpers ---------------------------------------------------
__device__ __forceinline__ uint32_t s2u(const void* p) {
    uint32_t r;
    asm("{.reg .u64 t; cvta.to.shared.u64 t, %1; cvt.u32.u64 %0, t;}" : "=r"(r) : "l"(p));
    return r;
}
__device__ __forceinline__ uint32_t swz(uint32_t b) { return b ^ ((b >> 3) & 0x70); }

__device__ __forceinline__ void cpa16h(uint32_t daddr, const __half* src, bool pred) {
    int sz = pred ? 16 : 0;
    asm volatile("cp.async.cg.shared.global [%0], [%1], 16, %2;\n"
                 :: "r"(daddr), "l"(src), "r"(sz));
}
__device__ __forceinline__ void cp_commit() {
    asm volatile("cp.async.commit_group;\n" ::);
}
template<int N> __device__ __forceinline__ void cp_wait() {
    asm volatile("cp.async.wait_group %0;\n" :: "n"(N));
}
__device__ __forceinline__ void sts32(uint32_t addr, uint32_t v) {
    asm volatile("st.shared.b32 [%0], %1;" :: "r"(addr), "r"(v) : "memory");
}
__device__ __forceinline__ void mma16(float* c, const uint32_t* a, const uint32_t* b) {
    asm volatile(
        "mma.sync.aligned.m16n8k16.row.col.f32.f16.f16.f32 "
        "{%0,%1,%2,%3}, {%4,%5,%6,%7}, {%8,%9}, {%0,%1,%2,%3};"
        : "+f"(c[0]), "+f"(c[1]), "+f"(c[2]), "+f"(c[3])
        : "r"(a[0]), "r"(a[1]), "r"(a[2]), "r"(a[3]), "r"(b[0]), "r"(b[1]));
}
__device__ __forceinline__ float silu_mul(float g, float u) {
    return g / (1.f + __expf(-g)) * u;
}
__device__ __forceinline__ void ldsm4(uint32_t* r, uint32_t addr) {
    asm volatile("ldmatrix.sync.aligned.m8n8.x4.shared.b16 {%0,%1,%2,%3}, [%4];"
        : "=r"(r[0]), "=r"(r[1]), "=r"(r[2]), "=r"(r[3]) : "r"(addr));
}

#define TILE_BYTES 16384u
#define SMEM_GU3  (3 * 3 * TILE_BYTES)      // 144 KB (gu fused)
#define SMEM_FIN  (3 * 3 * TILE_BYTES)      // 144 KB (final 128x256, 3-stage)

// single-B k64 compute, warp tile 32x64 (for final)
__device__ __forceinline__ void compute_k64h(
    uint32_t sAt, uint32_t sBt, int wm, int wn, int lane, float acc[2][8][4]) {
    int ar = lane & 15, ac = lane >> 4;
    int br = (lane & 7) + ((lane >> 4) & 1) * 8;
    int bc = (lane >> 3) & 1;
#pragma unroll
    for (int ks = 0; ks < 4; ks++) {
        uint32_t af[2][4];
#pragma unroll
        for (int mt = 0; mt < 2; mt++)
            ldsm4(af[mt], sAt + swz((uint32_t)((wm + mt * 16 + ar) * 128 + (ks * 2 + ac) * 16)));
        uint32_t bf[8][2];
#pragma unroll
        for (int j = 0; j < 4; j++) {
            uint32_t r[4];
            ldsm4(r, sBt + swz((uint32_t)((wn + 16 * j + br) * 128 + (ks * 2 + bc) * 16)));
            bf[2*j][0] = r[0]; bf[2*j][1] = r[1]; bf[2*j+1][0] = r[2]; bf[2*j+1][1] = r[3];
        }
#pragma unroll
        for (int mt = 0; mt < 2; mt++)
#pragma unroll
            for (int nt = 0; nt < 8; nt++) mma16(acc[mt][nt], af[mt], bf[nt]);
    }
}

// single-B k64 compute, warp tile 32x32 (down phase, 16 warps over 128 cols)
__device__ __forceinline__ void compute_k64h_32(
    uint32_t sAt, uint32_t sBt, int wm, int wn, int lane, float acc[2][4][4]) {
    int ar = lane & 15, ac = lane >> 4;
    int br = (lane & 7) + ((lane >> 4) & 1) * 8;
    int bc = (lane >> 3) & 1;
#pragma unroll
    for (int ks = 0; ks < 4; ks++) {
        uint32_t af[2][4];
#pragma unroll
        for (int mt = 0; mt < 2; mt++)
            ldsm4(af[mt], sAt + swz((uint32_t)((wm + mt * 16 + ar) * 128 + (ks * 2 + ac) * 16)));
        uint32_t bf[4][2];
#pragma unroll
        for (int j = 0; j < 2; j++) {
            uint32_t r[4];
            ldsm4(r, sBt + swz((uint32_t)((wn + 16 * j + br) * 128 + (ks * 2 + bc) * 16)));
            bf[2*j][0] = r[0]; bf[2*j][1] = r[1]; bf[2*j+1][0] = r[2]; bf[2*j+1][1] = r[3];
        }
#pragma unroll
        for (int mt = 0; mt < 2; mt++)
#pragma unroll
            for (int nt = 0; nt < 4; nt++) mma16(acc[mt][nt], af[mt], bf[nt]);
    }
}

// fused gate+up compute, 512 threads: warp tile 32x32 per output matrix
__device__ __forceinline__ void compute_k64h_gu512(
    uint32_t sAt, uint32_t sBg, uint32_t sBu, int wm, int wn, int lane,
    float accg[2][4][4], float accu[2][4][4]) {
    int ar = lane & 15, ac = lane >> 4;
    int br = (lane & 7) + ((lane >> 4) & 1) * 8;
    int bc = (lane >> 3) & 1;
#pragma unroll
    for (int ks = 0; ks < 4; ks++) {
        uint32_t af[2][4];
#pragma unroll
        for (int mt = 0; mt < 2; mt++)
            ldsm4(af[mt], sAt + swz((uint32_t)((wm + mt * 16 + ar) * 128 + (ks * 2 + ac) * 16)));
        uint32_t bf[4][2];
#pragma unroll
        for (int j = 0; j < 2; j++) {
            uint32_t r[4];
            ldsm4(r, sBg + swz((uint32_t)((wn + 16 * j + br) * 128 + (ks * 2 + bc) * 16)));
            bf[2*j][0] = r[0]; bf[2*j][1] = r[1]; bf[2*j+1][0] = r[2]; bf[2*j+1][1] = r[3];
        }
#pragma unroll
        for (int mt = 0; mt < 2; mt++)
#pragma unroll
            for (int nt = 0; nt < 4; nt++) mma16(accg[mt][nt], af[mt], bf[nt]);
#pragma unroll
        for (int j = 0; j < 2; j++) {
            uint32_t r[4];
            ldsm4(r, sBu + swz((uint32_t)((wn + 16 * j + br) * 128 + (ks * 2 + bc) * 16)));
            bf[2*j][0] = r[0]; bf[2*j][1] = r[1]; bf[2*j+1][0] = r[2]; bf[2*j+1][1] = r[3];
        }
#pragma unroll
        for (int mt = 0; mt < 2; mt++)
#pragma unroll
            for (int nt = 0; nt < 4; nt++) mma16(accu[mt][nt], af[mt], bf[nt]);
    }
}

// ---------------- K0: convW (6 weight arrays, 32 floats/thread) + init --------
#define NG8  ((unsigned)(NEXP * HID * DIM / 8))
#define NS8  ((unsigned)(SHID * DIM / 8))
#define W1 (NG8)
#define W2 (2u * NG8)
#define W3 (3u * NG8)
#define W4 (W3 + NS8)
#define W5 (W4 + NS8)
#define W6 (W5 + NS8)

__global__ __launch_bounds__(256) void convw_kernel(
    const float* __restrict__ gw, const float* __restrict__ uw,
    const float* __restrict__ dw, const float* __restrict__ sgw,
    const float* __restrict__ suw, const float* __restrict__ sdw) {
    if (blockIdx.x == 0 && threadIdx.x < NEXP) g_cursor[threadIdx.x] = 0;
    unsigned q = (blockIdx.x * 256 + threadIdx.x) * 4;
    if (q >= W6) return;
    const float* src; __half* dst; unsigned base;
    if      (q < W1) { src = gw;  dst = g_gwh;  base = 0; }
    else if (q < W2) { src = uw;  dst = g_uwh;  base = W1; }
    else if (q < W3) { src = dw;  dst = g_dwh;  base = W2; }
    else if (q < W4) { src = sgw; dst = g_sgwh; base = W3; }
    else if (q < W5) { src = suw; dst = g_suwh; base = W4; }
    else             { src = sdw; dst = g_sdwh; base = W5; }
    size_t e = (size_t)(q - base) * 8;
    const float4* s = (const float4*)(src + e);
    float4 v[8];
#pragma unroll
    for (int i = 0; i < 8; i++) v[i] = s[i];
#pragma unroll
    for (int i = 0; i < 4; i++) {
        __half2 h[4];
        h[0] = __floats2half2_rn(v[2*i].x, v[2*i].y);
        h[1] = __floats2half2_rn(v[2*i].z, v[2*i].w);
        h[2] = __floats2half2_rn(v[2*i+1].x, v[2*i+1].y);
        h[3] = __floats2half2_rn(v[2*i+1].z, v[2*i+1].w);
        *(uint4*)(dst + e + i * 8) = *(uint4*)h;
    }
}

// ---------------- K1: router + softmax + top4 + scatter + x->fp16 -------------
__global__ __launch_bounds__(256) void router_scatter_kernel(
    const float* __restrict__ x, const float* __restrict__ rw,
    const float* __restrict__ rb) {
    __shared__ float xs[8 * DIM];
    int tok0 = blockIdx.x * 8;
    int t = threadIdx.x;
#pragma unroll
    for (int i = 0; i < 8; i++) {
        int s = t + i * 256;
        int r = s >> 8; int q = s & 255;
        *(float4*)(xs + r * DIM + q * 4) =
            *(const float4*)(x + (size_t)(tok0 + r) * DIM + q * 4);
    }
    __syncthreads();
#pragma unroll
    for (int i = 0; i < 4; i++) {
        int c = (t + i * 256) * 8;
        const float4* sv = (const float4*)(xs + c);
        float4 a = sv[0], b = sv[1];
        __half2 h[4];
        h[0] = __floats2half2_rn(a.x, a.y); h[1] = __floats2half2_rn(a.z, a.w);
        h[2] = __floats2half2_rn(b.x, b.y); h[3] = __floats2half2_rn(b.z, b.w);
        *(uint4*)(g_xh + (size_t)tok0 * DIM + c) = *(uint4*)h;
    }
    int tl = t >> 5, lane = t & 31;
    int tok = tok0 + tl;
    float acc = rb[lane];
    const float4* xv = (const float4*)(xs + tl * DIM);
    const float4* wv = (const float4*)(rw + (size_t)lane * DIM);
#pragma unroll 4
    for (int q = 0; q < DIM / 4; q++) {
        float4 a = xv[q], b = wv[q];
        acc = fmaf(a.x, b.x, acc); acc = fmaf(a.y, b.y, acc);
        acc = fmaf(a.z, b.z, acc); acc = fmaf(a.w, b.w, acc);
    }
    float m = acc;
#pragma unroll
    for (int o = 16; o; o >>= 1) m = fmaxf(m, __shfl_xor_sync(~0u, m, o));
    float p = __expf(acc - m);
    float s = p;
#pragma unroll
    for (int o = 16; o; o >>= 1) s += __shfl_xor_sync(~0u, s, o);
    float sc = p / s;
    float cs[TK]; int ci[TK];
    float cur = sc;
#pragma unroll
    for (int k = 0; k < TK; k++) {
        float v = cur; int vi = lane;
#pragma unroll
        for (int o = 16; o; o >>= 1) {
            float ov = __shfl_xor_sync(~0u, v, o);
            int   oi = __shfl_xor_sync(~0u, vi, o);
            if (ov > v || (ov == v && oi < vi)) { v = ov; vi = oi; }
        }
        cs[k] = v; ci[k] = vi;
        if (lane == vi) cur = -1.f;
    }
    float inv = 1.f / fmaxf(cs[0] + cs[1] + cs[2] + cs[3], 1e-12f);
    if (lane < TK) {
        int e = ci[lane];
        int pos = atomicAdd(&g_cursor[e], 1);
        g_bucket_src[(size_t)e * CAP + pos] = tok * TK + lane;
        g_bucket_sc [(size_t)e * CAP + pos] = cs[lane] * inv;
    }
}

// ---------------- K2: FUSED gate+up+SiLU(+down for routed) --------------------
// grid (64, NEXP + 4). routed: full expert FFN tile -> Y. shared: gate/up -> sH.
__global__ __launch_bounds__(512) void gu_all_kernel(
    const __half* __restrict__ gwp, const __half* __restrict__ uwp,
    const __half* __restrict__ sgwp, const __half* __restrict__ suwp,
    const __half* __restrict__ dwp) {
    int by = blockIdx.y;
    int tile0 = blockIdx.x * 128;
    int t = threadIdx.x;
    extern __shared__ __half smh[];
    uint32_t sA = s2u(smh), sBg = sA + 3 * TILE_BYTES, sBu = sA + 6 * TILE_BYTES;
    __shared__ int srcs[128];
    __shared__ float scs[128];

    bool routed = by < NEXP;
    int cnt;
    const __half *Wg, *Wu;
    if (routed) {
        cnt = g_cursor[by];
        if (tile0 >= cnt) return;
        size_t off = (size_t)by * CAP;
        Wg = gwp + (size_t)by * HID * DIM;
        Wu = uwp + (size_t)by * HID * DIM;
        if (t < 128) {
            int m = tile0 + t;
            bool v = m < cnt;
            srcs[t] = v ? g_bucket_src[off + m] : -1;
            scs[t]  = v ? g_bucket_sc[off + m] : 0.f;
        }
    } else {
        int nb = (by - NEXP) * 128;
        cnt = NTOK;
        Wg = sgwp + (size_t)nb * DIM;
        Wu = suwp + (size_t)nb * DIM;
        if (t < 128) srcs[t] = tile0 + t;
    }
    __syncthreads();

    int shift = routed ? 2 : 0;
    int rw_[2], cw[2]; const __half* aP[2]; const __half* gP[2]; const __half* uP[2]; bool av[2];
#pragma unroll
    for (int i = 0; i < 2; i++) {
        int c = t + i * 512; rw_[i] = c >> 3; cw[i] = c & 7;
        int s0 = srcs[rw_[i]];
        av[i] = s0 >= 0;
        int tok = (av[i] ? s0 : 0) >> shift;
        aP[i] = g_xh + (size_t)tok * DIM + cw[i] * 8;
        gP[i] = Wg + (size_t)rw_[i] * DIM + cw[i] * 8;
        uP[i] = Wu + (size_t)rw_[i] * DIM + cw[i] * 8;
    }
    int lane = t & 31, wid = t >> 5;
    int wm = (wid & 3) * 32, wn = (wid >> 2) * 32, g = lane >> 2, tig = lane & 3;
    float accg[2][4][4] = {}, accu[2][4][4] = {};

#define GU_ISSUE(st, kb)                                                        \
    {                                                                           \
        uint32_t so = (uint32_t)(st) * TILE_BYTES;                              \
        _Pragma("unroll")                                                       \
        for (int i = 0; i < 2; i++) {                                           \
            uint32_t o = swz((uint32_t)(rw_[i] * 128 + cw[i] * 16));            \
            cpa16h(sA + so + o, aP[i] + (kb), av[i]);                           \
            cpa16h(sBg + so + o, gP[i] + (kb), true);                           \
            cpa16h(sBu + so + o, uP[i] + (kb), true);                           \
        }                                                                       \
        cp_commit();                                                            \
    }

    const int NIT = DIM / 64;     // 16
    GU_ISSUE(0, 0) GU_ISSUE(1, 64)
    for (int it = 0; it < NIT; it++) {
        if (it + 1 < NIT) cp_wait<1>(); else cp_wait<0>();
        __syncthreads();
        int st = it % 3;
        compute_k64h_gu512(sA + st * TILE_BYTES, sBg + st * TILE_BYTES,
                           sBu + st * TILE_BYTES, wm, wn, lane, accg, accu);
        int nx = it + 2;
        if (nx < NIT) GU_ISSUE(nx % 3, nx * 64)
    }
#undef GU_ISSUE

    if (!routed) {
        // shared epilogue: SiLU -> g_sHh, done
        int nb = (by - NEXP) * 128;
        __half* outp = g_sHh + nb;
#pragma unroll
        for (int mt = 0; mt < 2; mt++) {
            int rA = tile0 + wm + mt * 16 + g;
#pragma unroll
            for (int nt = 0; nt < 4; nt++) {
                int col = wn + nt * 8 + 2 * tig;
                __half2 h0 = __floats2half2_rn(
                    silu_mul(accg[mt][nt][0], accu[mt][nt][0]),
                    silu_mul(accg[mt][nt][1], accu[mt][nt][1]));
                *(__half2*)(outp + (size_t)rA * SHID + col) = h0;
                __half2 h1 = __floats2half2_rn(
                    silu_mul(accg[mt][nt][2], accu[mt][nt][2]),
                    silu_mul(accg[mt][nt][3], accu[mt][nt][3]));
                *(__half2*)(outp + (size_t)(rA + 8) * SHID + col) = h1;
            }
        }
        return;
    }

    // ---- routed: in-CTA down GEMM ----
    __syncthreads();   // all warps done reading pipeline buffers

    // W chunk loaders (512 thr x 2 chunks per 16KB tile)
    const __half* W = dwp + (size_t)by * DIM * HID;
#define WD_ISSUE(j)                                                             \
    {                                                                           \
        int nbv = (j) >> 1, kv = (j) & 1;                                       \
        uint32_t slot = ((uint32_t)(j) % 3) * TILE_BYTES;                       \
        _Pragma("unroll")                                                       \
        for (int i = 0; i < 2; i++) {                                           \
            uint32_t o = swz((uint32_t)(rw_[i] * 128 + cw[i] * 16));            \
            cpa16h(sBg + slot + o,                                              \
                   W + (size_t)(nbv * 128 + rw_[i]) * HID + kv * 64 + cw[i] * 8, true); \
        }                                                                       \
        cp_commit();                                                            \
    }
    WD_ISSUE(0) WD_ISSUE(1)

    // write H (SiLU) into sA slots 0 (cols 0..63) and 1 (cols 64..127)
#pragma unroll
    for (int mt = 0; mt < 2; mt++) {
        int rL = wm + mt * 16 + g;
#pragma unroll
        for (int nt = 0; nt < 4; nt++) {
            int col = wn + nt * 8 + 2 * tig;
            uint32_t chunk = (uint32_t)(col >> 6);
            uint32_t colb = (uint32_t)((col & 63) * 2);
            __half2 h0 = __floats2half2_rn(
                silu_mul(accg[mt][nt][0], accu[mt][nt][0]),
                silu_mul(accg[mt][nt][1], accu[mt][nt][1]));
            sts32(sA + chunk * TILE_BYTES +
                  (((uint32_t)rL * 128 + colb) ^ (((uint32_t)rL & 7) << 4)),
                  *(uint32_t*)&h0);
            int rH = rL + 8;
            __half2 h1 = __floats2half2_rn(
                silu_mul(accg[mt][nt][2], accu[mt][nt][2]),
                silu_mul(accg[mt][nt][3], accu[mt][nt][3]));
            sts32(sA + chunk * TILE_BYTES +
                  (((uint32_t)rH * 128 + colb) ^ (((uint32_t)rH & 7) << 4)),
                  *(uint32_t*)&h1);
        }
    }
    __syncthreads();

    float acc[2][4][4] = {};
    for (int j = 0; j < 16; j++) {
        if (j + 1 < 16) cp_wait<1>(); else cp_wait<0>();
        __syncthreads();
        compute_k64h_32(sA + (j & 1) * TILE_BYTES, sBg + (j % 3) * TILE_BYTES,
                        wm, wn, lane, acc);
        int nx = j + 2;
        if (nx < 16) WD_ISSUE(nx)
        if (j & 1) {
            int nb = j >> 1;
#pragma unroll
            for (int mt = 0; mt < 2; mt++) {
                int rL = wm + mt * 16 + g;
                int s0 = srcs[rL], s1 = srcs[rL + 8];
#pragma unroll
                for (int nt = 0; nt < 4; nt++) {
                    int col = nb * 128 + wn + nt * 8 + 2 * tig;
                    if (s0 >= 0) {
                        float s = scs[rL];
                        *(__half2*)(g_Y + (size_t)s0 * DIM + col) =
                            __floats2half2_rn(acc[mt][nt][0] * s, acc[mt][nt][1] * s);
                    }
                    if (s1 >= 0) {
                        float s = scs[rL + 8];
                        *(__half2*)(g_Y + (size_t)s1 * DIM + col) =
                            __floats2half2_rn(acc[mt][nt][2] * s, acc[mt][nt][3] * s);
                    }
                }
            }
#pragma unroll
            for (int mt = 0; mt < 2; mt++)
#pragma unroll
                for (int nt = 0; nt < 4; nt++)
#pragma unroll
                    for (int v = 0; v < 4; v++) acc[mt][nt][v] = 0.f;
        }
    }
#undef WD_ISSUE
}

// ---------------- K3: final GEMM 128x256 (512 thr) + Y gather -> out -----------
__global__ __launch_bounds__(512) void final_kernel(
    const __half* __restrict__ sdwp, float* __restrict__ out) {
    int tile0 = blockIdx.x * 128;
    int nb = blockIdx.y * 256;
    extern __shared__ __half smh[];
    uint32_t sA = s2u(smh);
    uint32_t sB = sA + 3 * TILE_BYTES;
    int t = threadIdx.x;

    int arw[2], acw[2]; const __half* aP[2];
#pragma unroll
    for (int i = 0; i < 2; i++) {
        int c = t + i * 512; arw[i] = c >> 3; acw[i] = c & 7;
        aP[i] = g_sHh + (size_t)(tile0 + arw[i]) * SHID + acw[i] * 8;
    }
    int brw[4], bcw[4]; const __half* bP[4];
#pragma unroll
    for (int i = 0; i < 4; i++) {
        int c = t + i * 512; brw[i] = c >> 3; bcw[i] = c & 7;
        bP[i] = sdwp + (size_t)(nb + brw[i]) * SHID + bcw[i] * 8;
    }
    int lane = t & 31, wid = t >> 5;
    int wm = (wid & 3) * 32, wn = (wid >> 2) * 64, g = lane >> 2, tig = lane & 3;
    float acc[2][8][4] = {};

#define FIN_ISSUE(st, kb)                                                       \
    {                                                                           \
        uint32_t soA = (uint32_t)(st) * TILE_BYTES;                             \
        uint32_t soB = (uint32_t)(st) * 2 * TILE_BYTES;                         \
        _Pragma("unroll")                                                       \
        for (int i = 0; i < 2; i++)                                             \
            cpa16h(sA + soA + swz((uint32_t)(arw[i] * 128 + acw[i] * 16)),      \
                   aP[i] + (kb), true);                                         \
        _Pragma("unroll")                                                       \
        for (int i = 0; i < 4; i++)                                             \
            cpa16h(sB + soB + swz((uint32_t)(brw[i] * 128 + bcw[i] * 16)),      \
                   bP[i] + (kb), true);                                         \
        cp_commit();                                                            \
    }

    {
        const int NIT = SHID / 64;
        FIN_ISSUE(0, 0) FIN_ISSUE(1, 64)
        for (int it = 0; it < NIT; it++) {
            if (it + 1 < NIT) cp_wait<1>(); else cp_wait<0>();
            __syncthreads();
            int st = it % 3;
            compute_k64h(sA + st * TILE_BYTES, sB + st * 2 * TILE_BYTES, wm, wn, lane, acc);
            int nx = it + 2;
            if (nx < NIT) FIN_ISSUE(nx % 3, nx * 64)
        }
    }
#undef FIN_ISSUE

#pragma unroll
    for (int mt = 0; mt < 2; mt++) {
        int r0 = tile0 + wm + mt * 16 + g;
        const __half* ya = g_Y + (size_t)r0 * TK * DIM;
#pragma unroll
        for (int nt = 0; nt < 8; nt++) {
            int col = nb + wn + nt * 8 + 2 * tig;
            float2 f0 = __half22float2(*(const __half2*)(ya + col));
            float2 f1 = __half22float2(*(const __half2*)(ya + DIM + col));
            float2 f2 = __half22float2(*(const __half2*)(ya + 2 * DIM + col));
            float2 f3 = __half22float2(*(const __half2*)(ya + 3 * DIM + col));
            float2 ra;
            ra.x = acc[mt][nt][0] + f0.x + f1.x + f2.x + f3.x;
            ra.y = acc[mt][nt][1] + f0.y + f1.y + f2.y + f3.y;
            *(float2*)(out + (size_t)r0 * DIM + col) = ra;
            const __half* yb = ya + 8 * TK * DIM;
            float2 z0 = __half22float2(*(const __half2*)(yb + col));
            float2 z1 = __half22float2(*(const __half2*)(yb + DIM + col));
            float2 z2 = __half22float2(*(const __half2*)(yb + 2 * DIM + col));
            float2 z3 = __half22float2(*(const __half2*)(yb + 3 * DIM + col));
            float2 rb;
            rb.x = acc[mt][nt][2] + z0.x + z1.x + z2.x + z3.x;
            rb.y = acc[mt][nt][3] + z0.y + z1.y + z2.y + z3.y;
            *(float2*)(out + (size_t)(r0 + 8) * DIM + col) = rb;
        }
    }
}

// ---------------- launch ---------------------------------------------------------
extern "C" void kernel_launch(void* const* d_in, const int* in_sizes, int n_in,
                              void* d_out, int out_size) {
    const float* x   = (const float*)d_in[0];
    const float* rw  = (const float*)d_in[1];
    const float* rb  = (const float*)d_in[2];
    const float* gw  = (const float*)d_in[3];
    const float* uw  = (const float*)d_in[4];
    const float* dw  = (const float*)d_in[5];
    const float* sgw = (const float*)d_in[6];
    const float* suw = (const float*)d_in[7];
    const float* sdw = (const float*)d_in[8];
    float* out = (float*)d_out;

    static __half *p_gwh = nullptr, *p_uwh, *p_dwh, *p_sgwh, *p_suwh, *p_sdwh;
    if (!p_gwh) {
        cudaGetSymbolAddress((void**)&p_gwh,  g_gwh);
        cudaGetSymbolAddress((void**)&p_uwh,  g_uwh);
        cudaGetSymbolAddress((void**)&p_dwh,  g_dwh);
        cudaGetSymbolAddress((void**)&p_sgwh, g_sgwh);
        cudaGetSymbolAddress((void**)&p_suwh, g_suwh);
        cudaGetSymbolAddress((void**)&p_sdwh, g_sdwh);
    }

    cudaFuncSetAttribute(gu_all_kernel, cudaFuncAttributeMaxDynamicSharedMemorySize, SMEM_GU3);
    cudaFuncSetAttribute(final_kernel,  cudaFuncAttributeMaxDynamicSharedMemorySize, SMEM_FIN);

    convw_kernel<<<(W6 / 4 + 255) / 256, 256>>>(gw, uw, dw, sgw, suw, sdw);          // 0
    router_scatter_kernel<<<NTOK / 8, 256>>>(x, rw, rb);                             // 1
    gu_all_kernel<<<dim3(64, NEXP + 4), 512, SMEM_GU3>>>(p_gwh, p_uwh, p_sgwh, p_suwh, p_dwh); // 2
    final_kernel<<<dim3(64, 4), 512, SMEM_FIN>>>(p_sdwh, out);                       // 3
}